// round 15
// baseline (speedup 1.0000x reference)
#include <cuda_runtime.h>
#include <cuda_fp16.h>
#include <cuda_bf16.h>
#include <cstdint>
#include <cstddef>

#define PDIM 1100
#define DDIM 1024
#define ODIM 1024
#define NB   16
#define NLBL 5000
#define NROW (NB * NLBL)
#define HROW (NROW / 2)                    // rows per pass (2 passes)

// ---------------- scratch (static device globals; no runtime alloc) ----------------
__device__ float g_Pe[NB * DDIM];
__device__ float g_hp[NB * DDIM];        // hp = Pe @ W1_p^T + b1
__device__ float g_Wc[DDIM * DDIM];      // Wc = W1_l @ Wl
__device__ float g_hl[NLBL * DDIM];      // hl = labels @ Wc^T
__device__ __align__(16) __nv_bfloat16 g_LBh[NLBL * DDIM];
__device__ __align__(16) __nv_bfloat16 g_LBl[NLBL * DDIM];
__device__ __align__(16) __nv_bfloat16 g_WTh[DDIM * DDIM];
__device__ __align__(16) __nv_bfloat16 g_WTl[DDIM * DDIM];
__device__ __align__(16) __nv_bfloat16 g_W1h[DDIM * DDIM];
__device__ __align__(16) __nv_bfloat16 g_W1l[DDIM * DDIM];
__device__ __align__(16) __nv_bfloat16 g_Wch[DDIM * DDIM];
__device__ __align__(16) __nv_bfloat16 g_Wcl[DDIM * DDIM];
__device__ __align__(16) __half g_W2f[ODIM * DDIM];            // fp16 W2
__device__ __align__(16) __half g_h16[(size_t)HROW * DDIM];    // fp16 h, half batch

// ---------------- pack helpers ----------------
__device__ __forceinline__ unsigned pack_bf2(float lo_elem, float hi_elem) {
    unsigned r;
    asm("cvt.rn.bf16x2.f32 %0, %1, %2;" : "=r"(r) : "f"(hi_elem), "f"(lo_elem));
    return r;
}
__device__ __forceinline__ unsigned pack_h2(float lo_elem, float hi_elem) {
    unsigned r;
    asm("cvt.rn.f16x2.f32 %0, %1, %2;" : "=r"(r) : "f"(hi_elem), "f"(lo_elem));
    return r;
}
__device__ __forceinline__ float lo16f(unsigned u) { return __uint_as_float(u << 16); }
__device__ __forceinline__ float hi16f(unsigned u) { return __uint_as_float(u & 0xffff0000u); }

// ---------------- mma.sync + ldmatrix + cp.async (standard PTX, base sm_103) ----------------
__device__ __forceinline__ void mma_bf16(float* c, const unsigned* a, const unsigned* b) {
    asm volatile(
        "mma.sync.aligned.m16n8k16.row.col.f32.bf16.bf16.f32 "
        "{%0,%1,%2,%3}, {%4,%5,%6,%7}, {%8,%9}, {%0,%1,%2,%3};"
        : "+f"(c[0]), "+f"(c[1]), "+f"(c[2]), "+f"(c[3])
        : "r"(a[0]), "r"(a[1]), "r"(a[2]), "r"(a[3]), "r"(b[0]), "r"(b[1]));
}
__device__ __forceinline__ void mma_f16(float* c, const unsigned* a, const unsigned* b) {
    asm volatile(
        "mma.sync.aligned.m16n8k16.row.col.f32.f16.f16.f32 "
        "{%0,%1,%2,%3}, {%4,%5,%6,%7}, {%8,%9}, {%0,%1,%2,%3};"
        : "+f"(c[0]), "+f"(c[1]), "+f"(c[2]), "+f"(c[3])
        : "r"(a[0]), "r"(a[1]), "r"(a[2]), "r"(a[3]), "r"(b[0]), "r"(b[1]));
}
__device__ __forceinline__ void ldsm4(unsigned* r, uint32_t addr) {
    asm volatile("ldmatrix.sync.aligned.m8n8.x4.shared.b16 {%0,%1,%2,%3}, [%4];"
                 : "=r"(r[0]), "=r"(r[1]), "=r"(r[2]), "=r"(r[3]) : "r"(addr));
}
__device__ __forceinline__ uint32_t smem_to_u32(const void* p) {
    uint32_t a;
    asm("{ .reg .u64 t; cvta.to.shared.u64 t, %1; cvt.u32.u64 %0, t; }" : "=r"(a) : "l"(p));
    return a;
}
#define CP_ASYNC16(dst, src) \
    asm volatile("cp.async.cg.shared.global [%0], [%1], 16;" :: "r"(dst), "l"(src))
#define CP_COMMIT() asm volatile("cp.async.commit_group;" ::: "memory")
#define CP_WAIT0()  asm volatile("cp.async.wait_group 0;" ::: "memory")

#define APAD 72   // 144 B rows -> conflict-free ldmatrix phases

// ---------------- kernel 1a: Pe[b, :] = seq[b, :] @ Wp^T ----------------
__global__ __launch_bounds__(256) void pe_kernel(const float* __restrict__ seq,
                                                 const float* __restrict__ Wp,
                                                 float* __restrict__ Pe) {
    __shared__ float s[PDIM];
    const int b = blockIdx.x, tid = threadIdx.x;
    for (int i = tid; i < PDIM; i += 256) s[i] = seq[b * PDIM + i];
    __syncthreads();
    const int warp = tid >> 5, lane = tid & 31;
    for (int d = warp; d < DDIM; d += 8) {
        const float* wrow = Wp + (size_t)d * PDIM;
        float p = 0.f;
        for (int k = lane; k < PDIM; k += 32) p = fmaf(s[k], wrow[k], p);
        #pragma unroll
        for (int off = 16; off > 0; off >>= 1) p += __shfl_down_sync(0xffffffffu, p, off);
        if (lane == 0) Pe[b * DDIM + d] = p;
    }
}

// ---------------- kernel 1b: hp[b, :] = Pe[b, :] @ W1_p^T + b1 ----------------
__global__ __launch_bounds__(256) void hp_kernel(const float* __restrict__ Pe,
                                                 const float* __restrict__ W1,
                                                 const float* __restrict__ b1,
                                                 float* __restrict__ hp) {
    __shared__ float s[DDIM];
    const int b = blockIdx.x, tid = threadIdx.x;
    for (int i = tid; i < DDIM; i += 256) s[i] = Pe[b * DDIM + i];
    __syncthreads();
    const int warp = tid >> 5, lane = tid & 31;
    for (int o = warp; o < ODIM; o += 8) {
        const float* wrow = W1 + (size_t)o * (2 * DDIM);
        float p = 0.f;
        for (int k = lane; k < DDIM; k += 32) p = fmaf(s[k], wrow[k], p);
        #pragma unroll
        for (int off = 16; off > 0; off >>= 1) p += __shfl_down_sync(0xffffffffu, p, off);
        if (lane == 0) hp[b * DDIM + o] = p + b1[o];
    }
}

// ---------------- split: fp32 rows (stride ld) -> bf16 hi/lo ----------------
__global__ __launch_bounds__(256) void split_kernel(const float* __restrict__ src, int ld,
                                                    __nv_bfloat16* __restrict__ h,
                                                    __nv_bfloat16* __restrict__ l) {
    const int row = blockIdx.x;
    const int c4 = threadIdx.x;
    float4 v = *(const float4*)(src + (size_t)row * ld + c4 * 4);
    unsigned h0 = pack_bf2(v.x, v.y);
    unsigned h1 = pack_bf2(v.z, v.w);
    unsigned l0 = pack_bf2(v.x - lo16f(h0), v.y - hi16f(h0));
    unsigned l1 = pack_bf2(v.z - lo16f(h1), v.w - hi16f(h1));
    *(uint2*)(h + (size_t)row * DDIM + c4 * 4) = make_uint2(h0, h1);
    *(uint2*)(l + (size_t)row * DDIM + c4 * 4) = make_uint2(l0, l1);
}

// ---------------- transpose-split: out[l][d] = src[d][l], bf16 hi/lo ----------------
__global__ __launch_bounds__(256) void tsplit_kernel(const float* __restrict__ src,
                                                     __nv_bfloat16* __restrict__ h,
                                                     __nv_bfloat16* __restrict__ l) {
    __shared__ float t[32][33];
    const int bx = blockIdx.x * 32;
    const int by = blockIdx.y * 32;
    const int tx = threadIdx.x & 31, ty = threadIdx.x >> 5;
    #pragma unroll
    for (int j = 0; j < 4; ++j)
        t[ty + j * 8][tx] = src[(size_t)(by + ty + j * 8) * DDIM + bx + tx];
    __syncthreads();
    #pragma unroll
    for (int j = 0; j < 4; ++j) {
        const int lrow = bx + ty + j * 8;
        const int dcol = by + tx;
        float v = t[tx][ty + j * 8];
        unsigned hb = pack_bf2(v, v);
        float hv = lo16f(hb);
        unsigned lb = pack_bf2(v - hv, v - hv);
        h[(size_t)lrow * DDIM + dcol] = *(__nv_bfloat16*)&hb;
        l[(size_t)lrow * DDIM + dcol] = *(__nv_bfloat16*)&lb;
    }
}

// ---------------- W2 -> fp16 ----------------
__global__ __launch_bounds__(256) void w2half_kernel(const float* __restrict__ W2,
                                                     __half* __restrict__ Wf) {
    int i = blockIdx.x * 256 + threadIdx.x;
    float4 v = ((const float4*)W2)[i];
    ((uint2*)Wf)[i] = make_uint2(pack_h2(v.x, v.y), pack_h2(v.z, v.w));
}

// ---------------- h16 build: h16[lrow][:] = fp16(relu(hp[b] + hl[l])) ----------------
// FIX vs R14: one row per block, 256 threads x float4 = full 1024 columns.
__global__ __launch_bounds__(256) void hbuild_kernel(const float* __restrict__ hp,
                                                     const float* __restrict__ hl,
                                                     __half* __restrict__ h16,
                                                     int row_off) {
    const int lrow = blockIdx.x;                 // local row in this pass
    const int c4 = threadIdx.x * 4;              // 256 thr x 4 = 1024 cols
    const int grow = row_off + lrow;
    const int b = grow / NLBL;
    const int l = grow - b * NLBL;
    float4 p = *(const float4*)(hp + (size_t)b * DDIM + c4);
    float4 q = *(const float4*)(hl + (size_t)l * DDIM + c4);
    *(uint2*)(h16 + (size_t)lrow * DDIM + c4) =
        make_uint2(pack_h2(fmaxf(p.x + q.x, 0.f), fmaxf(p.y + q.y, 0.f)),
                   pack_h2(fmaxf(p.z + q.z, 0.f), fmaxf(p.w + q.w, 0.f)));
}

// ---------------- tensor GEMM: C[M,1024] = A @ B^T, bf16 3-term, occ 2 ----------------
#define GM_SA_H 0
#define GM_SA_L (128 * APAD * 2)
#define GM_SB_H (2 * 128 * APAD * 2)
#define GM_SB_L (3 * 128 * APAD * 2)
#define GM_SMEM (4 * 128 * APAD * 2)     // 73728

__global__ __launch_bounds__(256, 2) void gemm_mma_kernel(
    const __nv_bfloat16* __restrict__ Ah_g, const __nv_bfloat16* __restrict__ Al_g,
    const __nv_bfloat16* __restrict__ Bh_g, const __nv_bfloat16* __restrict__ Bl_g,
    float* __restrict__ C, int M) {
    extern __shared__ __align__(128) char sm[];
    const uint32_t sb = smem_to_u32(sm);
    const uint32_t sAh = sb + GM_SA_H, sAl = sb + GM_SA_L;
    const uint32_t sBh = sb + GM_SB_H, sBl = sb + GM_SB_L;

    const int tid = threadIdx.x;
    const int lane = tid & 31;
    const int wid = tid >> 5;
    const int warp_m = wid & 1, warp_n = wid >> 1;
    const int gid = lane >> 2, tig = lane & 3;
    const int row0 = blockIdx.y * 128, col0 = blockIdx.x * 128;

    const int rowA = lane & 15;
    const int colA = (lane >> 4) * 8;
    const int rowB = (lane & 7) + ((lane & 16) >> 1);
    const int colB = lane & 8;
    const uint32_t aoffL = (uint32_t)(rowA * (APAD * 2) + colA * 2);
    const uint32_t boffL = (uint32_t)(rowB * (APAD * 2) + colB * 2);

    const int am = tid >> 1;
    const int half = (tid & 1) * 32;
    const int gr = row0 + am;
    const int gc = col0 + am;

    float acc[4][4][4];
    #pragma unroll
    for (int mt = 0; mt < 4; ++mt)
        #pragma unroll
        for (int ntl = 0; ntl < 4; ++ntl)
            #pragma unroll
            for (int c = 0; c < 4; ++c) acc[mt][ntl][c] = 0.f;

    for (int kc = 0; kc < 16; ++kc) {
        const int k0 = kc * 64;
        __syncthreads();
        {
            const uint32_t dof = (uint32_t)(am * (APAD * 2) + half * 2);
            if (gr < M) {
                const uint4* aH = (const uint4*)(Ah_g + (size_t)gr * DDIM + k0 + half);
                const uint4* aL = (const uint4*)(Al_g + (size_t)gr * DDIM + k0 + half);
                #pragma unroll
                for (int q = 0; q < 4; ++q) {
                    *(uint4*)(sm + GM_SA_H + dof + q * 16) = aH[q];
                    *(uint4*)(sm + GM_SA_L + dof + q * 16) = aL[q];
                }
            } else {
                uint4 z = make_uint4(0, 0, 0, 0);
                #pragma unroll
                for (int q = 0; q < 4; ++q) {
                    *(uint4*)(sm + GM_SA_H + dof + q * 16) = z;
                    *(uint4*)(sm + GM_SA_L + dof + q * 16) = z;
                }
            }
            const uint4* bH = (const uint4*)(Bh_g + (size_t)gc * DDIM + k0 + half);
            const uint4* bL = (const uint4*)(Bl_g + (size_t)gc * DDIM + k0 + half);
            #pragma unroll
            for (int q = 0; q < 4; ++q) {
                *(uint4*)(sm + GM_SB_H + dof + q * 16) = bH[q];
                *(uint4*)(sm + GM_SB_L + dof + q * 16) = bL[q];
            }
        }
        __syncthreads();
        #pragma unroll
        for (int s = 0; s < 4; ++s) {
            const uint32_t cb2 = (uint32_t)(s * 32);
            unsigned ahi[4][4], alo[4][4];
            #pragma unroll
            for (int mt = 0; mt < 4; ++mt) {
                const uint32_t ra =
                    (uint32_t)((warp_m * 64 + mt * 16) * (APAD * 2)) + aoffL + cb2;
                ldsm4(ahi[mt], sAh + ra);
                ldsm4(alo[mt], sAl + ra);
            }
            #pragma unroll
            for (int p = 0; p < 2; ++p) {
                const uint32_t rb =
                    (uint32_t)((warp_n * 32 + p * 16) * (APAD * 2)) + boffL + cb2;
                unsigned bh[4], bl[4];
                ldsm4(bh, sBh + rb);
                ldsm4(bl, sBl + rb);
                #pragma unroll
                for (int h = 0; h < 2; ++h) {
                    const unsigned* bhp = bh + h * 2;
                    const unsigned* blp = bl + h * 2;
                    const int ntl = p * 2 + h;
                    #pragma unroll
                    for (int mt = 0; mt < 4; ++mt) mma_bf16(acc[mt][ntl], ahi[mt], bhp);
                    #pragma unroll
                    for (int mt = 0; mt < 4; ++mt) mma_bf16(acc[mt][ntl], alo[mt], bhp);
                    #pragma unroll
                    for (int mt = 0; mt < 4; ++mt) mma_bf16(acc[mt][ntl], ahi[mt], blp);
                }
            }
        }
    }
    #pragma unroll
    for (int mt = 0; mt < 4; ++mt) {
        const int r1 = row0 + warp_m * 64 + mt * 16 + gid;
        #pragma unroll
        for (int ntl = 0; ntl < 4; ++ntl) {
            const int cc = col0 + warp_n * 32 + ntl * 8 + tig * 2;
            if (r1 < M)
                *(float2*)(C + (size_t)r1 * DDIM + cc) =
                    make_float2(acc[mt][ntl][0], acc[mt][ntl][1]);
            if (r1 + 8 < M)
                *(float2*)(C + (size_t)(r1 + 8) * DDIM + cc) =
                    make_float2(acc[mt][ntl][2], acc[mt][ntl][3]);
        }
    }
}

// ---------------- fused: h16 @ W2f^T (fp16) -> relu -> dot W3 ----------------
// M-tile 64, occ 2, A AND B via cp.async double buffers, one barrier per chunk.
#define FA_SZ  (64 * APAD * 2)            // 9216
#define FB_A   0                          // 2 x 9216 = 18432
#define FB_B   18432
#define FB_BSZ (256 * APAD * 2)           // 36864, x2 = 73728
#define FB_B2  (FB_B + 2 * FB_BSZ)        // 92160
#define FB_W3  (FB_B2 + 4096)
#define FB_LOG (FB_W3 + 4096)
#define FF_SMEM (FB_LOG + 256)            // 100608

__global__ __launch_bounds__(256, 2) void fused_f16_kernel(
    const __half* __restrict__ h16, const __half* __restrict__ W2f,
    const float* __restrict__ b2, const float* __restrict__ W3,
    const float* __restrict__ b3, float* __restrict__ out) {
    extern __shared__ __align__(128) char sm[];
    const uint32_t sb = smem_to_u32(sm);
    float* b2s    = (float*)(sm + FB_B2);
    float* w3s    = (float*)(sm + FB_W3);
    float* logits = (float*)(sm + FB_LOG);

    const int tid = threadIdx.x;
    const int lane = tid & 31;
    const int wid = tid >> 5;
    const int warp_m = wid & 1, warp_n = wid >> 1;
    const int gid = lane >> 2, tig = lane & 3;
    const int r0 = blockIdx.x * 64;       // local row within this pass

    const int rowA = lane & 15;
    const int colA = (lane >> 4) * 8;
    const int rowB = (lane & 7) + ((lane & 16) >> 1);
    const int colB = lane & 8;
    const uint32_t aoffL = (uint32_t)(rowA * (APAD * 2) + colA * 2);
    const uint32_t boffL = (uint32_t)(rowB * (APAD * 2) + colB * 2);

    for (int i = tid; i < ODIM; i += 256) { b2s[i] = b2[i]; w3s[i] = W3[i]; }
    if (tid < 64) logits[tid] = 0.f;

    // A prefetch mapping: 4 threads per row, 32 B (2 x 16B) each = 64-col chunk
    const int arow = tid >> 2;
    const int aseg = (tid & 3) * 32;
    const char* asrc0 = (const char*)(h16 + (size_t)(r0 + arow) * DDIM) + aseg;
    const uint32_t adst0 = sb + (uint32_t)(FB_A + arow * (APAD * 2) + aseg);
    // B prefetch mapping: one W2 row per thread
    const uint32_t bdst0 = sb + FB_B + (uint32_t)(tid * (APAD * 2));

    float pr[4];
    #pragma unroll
    for (int i = 0; i < 4; ++i) pr[i] = 0.f;

    // ---- prologue: chunk 0 (A + B) into buffer 0
    {
        CP_ASYNC16(adst0, asrc0);
        CP_ASYNC16(adst0 + 16, asrc0 + 16);
        const __half* src = W2f + (size_t)tid * DDIM;
        #pragma unroll
        for (int g = 0; g < 8; ++g) CP_ASYNC16(bdst0 + g * 16, (const char*)src + g * 16);
        CP_COMMIT();
        CP_WAIT0();
    }
    __syncthreads();

    for (int nt = 0; nt < 4; ++nt) {
        float acc[2][8][4];
        #pragma unroll
        for (int mt = 0; mt < 2; ++mt)
            #pragma unroll
            for (int ntl = 0; ntl < 8; ++ntl)
                #pragma unroll
                for (int c = 0; c < 4; ++c) acc[mt][ntl][c] = 0.f;

        for (int kc = 0; kc < 16; ++kc) {
            const int i = nt * 16 + kc;
            const int buf = i & 1;
            // ---- prefetch chunk i+1 (A + B) into other buffer, before mma
            if (i + 1 < 64) {
                const int ni = i + 1;
                const int nbuf = ni & 1;
                const int nk0 = (ni & 15) * 64;
                CP_ASYNC16(adst0 + nbuf * FA_SZ, asrc0 + nk0 * 2);
                CP_ASYNC16(adst0 + nbuf * FA_SZ + 16, asrc0 + nk0 * 2 + 16);
                const uint32_t dst = bdst0 + (uint32_t)(nbuf * FB_BSZ);
                const __half* src =
                    W2f + (size_t)((ni >> 4) * 256 + tid) * DDIM + nk0;
                #pragma unroll
                for (int g = 0; g < 8; ++g)
                    CP_ASYNC16(dst + g * 16, (const char*)src + g * 16);
                CP_COMMIT();
            }
            // ---- mma on current buffers
            const uint32_t sA = sb + (uint32_t)(FB_A + buf * FA_SZ);
            const uint32_t sB = sb + (uint32_t)(FB_B + buf * FB_BSZ);
            #pragma unroll
            for (int s = 0; s < 4; ++s) {
                const uint32_t cb2 = (uint32_t)(s * 32);
                unsigned af[2][4];
                #pragma unroll
                for (int mt = 0; mt < 2; ++mt) {
                    const uint32_t ra =
                        (uint32_t)((warp_m * 32 + mt * 16) * (APAD * 2)) + aoffL + cb2;
                    ldsm4(af[mt], sA + ra);
                }
                #pragma unroll
                for (int p = 0; p < 4; ++p) {
                    const uint32_t rb =
                        (uint32_t)((warp_n * 64 + p * 16) * (APAD * 2)) + boffL + cb2;
                    unsigned bf[4];
                    ldsm4(bf, sB + rb);
                    #pragma unroll
                    for (int h = 0; h < 2; ++h) {
                        const unsigned* bp = bf + h * 2;
                        const int ntl = p * 2 + h;
                        #pragma unroll
                        for (int mt = 0; mt < 2; ++mt) mma_f16(acc[mt][ntl], af[mt], bp);
                    }
                }
            }
            CP_WAIT0();
            __syncthreads();   // next chunk's A+B landed; buffers consistent
        }
        // ---- fold this 256-col tile: relu(acc + b2) * W3 -> per-row partials
        #pragma unroll
        for (int mt = 0; mt < 2; ++mt)
            #pragma unroll
            for (int ntl = 0; ntl < 8; ++ntl) {
                const int colb = nt * 256 + warp_n * 64 + ntl * 8 + tig * 2;
                #pragma unroll
                for (int c = 0; c < 4; ++c) {
                    const int cc = colb + (c & 1);
                    float v = acc[mt][ntl][c] + b2s[cc];
                    pr[mt * 2 + (c >> 1)] =
                        fmaf(fmaxf(v, 0.f), w3s[cc], pr[mt * 2 + (c >> 1)]);
                }
            }
    }

    // reduce over lane quads, then across the 4 N-warps via smem atomics
    #pragma unroll
    for (int i2 = 0; i2 < 4; ++i2) {
        float v = pr[i2];
        v += __shfl_xor_sync(0xffffffffu, v, 1);
        v += __shfl_xor_sync(0xffffffffu, v, 2);
        if ((lane & 3) == 0)
            atomicAdd(&logits[warp_m * 32 + (i2 >> 1) * 16 + (i2 & 1) * 8 + gid], v);
    }
    __syncthreads();
    if (tid < 64) out[r0 + tid] = logits[tid] + b3[0];
}

// ---------------- launch ----------------
extern "C" void kernel_launch(void* const* d_in, const int* in_sizes, int n_in,
                              void* d_out, int out_size) {
    const float* seq    = (const float*)d_in[0];
    const float* labels = (const float*)d_in[1];
    const float* Wp     = (const float*)d_in[2];
    const float* Wl     = (const float*)d_in[3];
    const float* W1     = (const float*)d_in[4];
    const float* b1     = (const float*)d_in[5];
    const float* W2     = (const float*)d_in[6];
    const float* b2     = (const float*)d_in[7];
    const float* W3     = (const float*)d_in[8];
    const float* b3     = (const float*)d_in[9];
    float* out = (float*)d_out;

    float *Pe, *hp, *Wc, *hl;
    __nv_bfloat16 *LBh, *LBl, *WTh, *WTl, *W1h, *W1l, *Wch, *Wcl;
    __half *W2f, *h16;
    cudaGetSymbolAddress((void**)&Pe, g_Pe);
    cudaGetSymbolAddress((void**)&hp, g_hp);
    cudaGetSymbolAddress((void**)&Wc, g_Wc);
    cudaGetSymbolAddress((void**)&hl, g_hl);
    cudaGetSymbolAddress((void**)&LBh, g_LBh);
    cudaGetSymbolAddress((void**)&LBl, g_LBl);
    cudaGetSymbolAddress((void**)&WTh, g_WTh);
    cudaGetSymbolAddress((void**)&WTl, g_WTl);
    cudaGetSymbolAddress((void**)&W1h, g_W1h);
    cudaGetSymbolAddress((void**)&W1l, g_W1l);
    cudaGetSymbolAddress((void**)&Wch, g_Wch);
    cudaGetSymbolAddress((void**)&Wcl, g_Wcl);
    cudaGetSymbolAddress((void**)&W2f, g_W2f);
    cudaGetSymbolAddress((void**)&h16, g_h16);

    pe_kernel<<<NB, 256>>>(seq, Wp, Pe);
    hp_kernel<<<NB, 256>>>(Pe, W1, b1, hp);

    // splits for the label-side algebra
    split_kernel<<<NLBL, 256>>>(labels, DDIM, LBh, LBl);
    split_kernel<<<DDIM, 256>>>(W1 + DDIM, 2 * DDIM, W1h, W1l);   // W1_l
    tsplit_kernel<<<dim3(32, 32), 256>>>(Wl, WTh, WTl);           // Wl^T

    cudaFuncSetAttribute(gemm_mma_kernel, cudaFuncAttributeMaxDynamicSharedMemorySize,
                         GM_SMEM);
    // Wc = W1_l @ Wl
    gemm_mma_kernel<<<dim3(8, 8), 256, GM_SMEM>>>(W1h, W1l, WTh, WTl, Wc, DDIM);
    split_kernel<<<DDIM, 256>>>(Wc, DDIM, Wch, Wcl);
    // hl = labels @ Wc^T
    gemm_mma_kernel<<<dim3(8, 40), 256, GM_SMEM>>>(LBh, LBl, Wch, Wcl, hl, NLBL);

    // W2 -> fp16
    w2half_kernel<<<(ODIM * DDIM / 4) / 256, 256>>>(W2, W2f);

    cudaFuncSetAttribute(fused_f16_kernel, cudaFuncAttributeMaxDynamicSharedMemorySize,
                         FF_SMEM);
    // two sequential half-batch passes reusing the h16 buffer
    for (int pass = 0; pass < 2; ++pass) {
        const int row_off = pass * HROW;
        hbuild_kernel<<<HROW, 256>>>(hp, hl, h16, row_off);
        fused_f16_kernel<<<HROW / 64, 256, FF_SMEM>>>(h16, W2f, b2, W3, b3,
                                                      out + row_off);
    }
}

// round 16
// speedup vs baseline: 1.0439x; 1.0439x over previous
#include <cuda_runtime.h>
#include <cuda_fp16.h>
#include <cuda_bf16.h>
#include <cstdint>
#include <cstddef>

#define PDIM 1100
#define DDIM 1024
#define ODIM 1024
#define NB   16
#define NLBL 5000
#define NROW (NB * NLBL)

// ---------------- scratch (static device globals; no runtime alloc) ----------------
__device__ float g_Pe[NB * DDIM];
__device__ float g_hp[NB * DDIM];        // hp = Pe @ W1_p^T + b1
__device__ float g_Wc[DDIM * DDIM];      // Wc = W1_l @ Wl
__device__ float g_hl[NLBL * DDIM];      // hl = labels @ Wc^T
__device__ __align__(16) __nv_bfloat16 g_LBh[NLBL * DDIM];
__device__ __align__(16) __nv_bfloat16 g_LBl[NLBL * DDIM];
__device__ __align__(16) __nv_bfloat16 g_WTh[DDIM * DDIM];
__device__ __align__(16) __nv_bfloat16 g_WTl[DDIM * DDIM];
__device__ __align__(16) __nv_bfloat16 g_W1h[DDIM * DDIM];
__device__ __align__(16) __nv_bfloat16 g_W1l[DDIM * DDIM];
__device__ __align__(16) __nv_bfloat16 g_Wch[DDIM * DDIM];
__device__ __align__(16) __nv_bfloat16 g_Wcl[DDIM * DDIM];
__device__ __align__(16) __half g_W2f[ODIM * DDIM];          // fp16 W2

// ---------------- pack helpers ----------------
__device__ __forceinline__ unsigned pack_bf2(float lo_elem, float hi_elem) {
    unsigned r;
    asm("cvt.rn.bf16x2.f32 %0, %1, %2;" : "=r"(r) : "f"(hi_elem), "f"(lo_elem));
    return r;
}
__device__ __forceinline__ unsigned pack_h2(float lo_elem, float hi_elem) {
    unsigned r;
    asm("cvt.rn.f16x2.f32 %0, %1, %2;" : "=r"(r) : "f"(hi_elem), "f"(lo_elem));
    return r;
}
__device__ __forceinline__ float lo16f(unsigned u) { return __uint_as_float(u << 16); }
__device__ __forceinline__ float hi16f(unsigned u) { return __uint_as_float(u & 0xffff0000u); }

// ---------------- mma.sync + ldmatrix + cp.async (standard PTX, base sm_103) ----------------
__device__ __forceinline__ void mma_bf16(float* c, const unsigned* a, const unsigned* b) {
    asm volatile(
        "mma.sync.aligned.m16n8k16.row.col.f32.bf16.bf16.f32 "
        "{%0,%1,%2,%3}, {%4,%5,%6,%7}, {%8,%9}, {%0,%1,%2,%3};"
        : "+f"(c[0]), "+f"(c[1]), "+f"(c[2]), "+f"(c[3])
        : "r"(a[0]), "r"(a[1]), "r"(a[2]), "r"(a[3]), "r"(b[0]), "r"(b[1]));
}
__device__ __forceinline__ void mma_f16(float* c, const unsigned* a, const unsigned* b) {
    asm volatile(
        "mma.sync.aligned.m16n8k16.row.col.f32.f16.f16.f32 "
        "{%0,%1,%2,%3}, {%4,%5,%6,%7}, {%8,%9}, {%0,%1,%2,%3};"
        : "+f"(c[0]), "+f"(c[1]), "+f"(c[2]), "+f"(c[3])
        : "r"(a[0]), "r"(a[1]), "r"(a[2]), "r"(a[3]), "r"(b[0]), "r"(b[1]));
}
__device__ __forceinline__ void ldsm4(unsigned* r, uint32_t addr) {
    asm volatile("ldmatrix.sync.aligned.m8n8.x4.shared.b16 {%0,%1,%2,%3}, [%4];"
                 : "=r"(r[0]), "=r"(r[1]), "=r"(r[2]), "=r"(r[3]) : "r"(addr));
}
__device__ __forceinline__ uint32_t smem_to_u32(const void* p) {
    uint32_t a;
    asm("{ .reg .u64 t; cvta.to.shared.u64 t, %1; cvt.u32.u64 %0, t; }" : "=r"(a) : "l"(p));
    return a;
}
#define CP_ASYNC16(dst, src) \
    asm volatile("cp.async.cg.shared.global [%0], [%1], 16;" :: "r"(dst), "l"(src))
#define CP_COMMIT() asm volatile("cp.async.commit_group;" ::: "memory")
#define CP_WAIT0()  asm volatile("cp.async.wait_group 0;" ::: "memory")

#define APAD 72   // 144 B rows -> conflict-free ldmatrix phases

// ---------------- kernel 1a: Pe[b, :] = seq[b, :] @ Wp^T ----------------
__global__ __launch_bounds__(256) void pe_kernel(const float* __restrict__ seq,
                                                 const float* __restrict__ Wp,
                                                 float* __restrict__ Pe) {
    __shared__ float s[PDIM];
    const int b = blockIdx.x, tid = threadIdx.x;
    for (int i = tid; i < PDIM; i += 256) s[i] = seq[b * PDIM + i];
    __syncthreads();
    const int warp = tid >> 5, lane = tid & 31;
    for (int d = warp; d < DDIM; d += 8) {
        const float* wrow = Wp + (size_t)d * PDIM;
        float p = 0.f;
        for (int k = lane; k < PDIM; k += 32) p = fmaf(s[k], wrow[k], p);
        #pragma unroll
        for (int off = 16; off > 0; off >>= 1) p += __shfl_down_sync(0xffffffffu, p, off);
        if (lane == 0) Pe[b * DDIM + d] = p;
    }
}

// ---------------- kernel 1b: hp[b, :] = Pe[b, :] @ W1_p^T + b1 ----------------
__global__ __launch_bounds__(256) void hp_kernel(const float* __restrict__ Pe,
                                                 const float* __restrict__ W1,
                                                 const float* __restrict__ b1,
                                                 float* __restrict__ hp) {
    __shared__ float s[DDIM];
    const int b = blockIdx.x, tid = threadIdx.x;
    for (int i = tid; i < DDIM; i += 256) s[i] = Pe[b * DDIM + i];
    __syncthreads();
    const int warp = tid >> 5, lane = tid & 31;
    for (int o = warp; o < ODIM; o += 8) {
        const float* wrow = W1 + (size_t)o * (2 * DDIM);
        float p = 0.f;
        for (int k = lane; k < DDIM; k += 32) p = fmaf(s[k], wrow[k], p);
        #pragma unroll
        for (int off = 16; off > 0; off >>= 1) p += __shfl_down_sync(0xffffffffu, p, off);
        if (lane == 0) hp[b * DDIM + o] = p + b1[o];
    }
}

// ---------------- split: fp32 rows (stride ld) -> bf16 hi/lo ----------------
__global__ __launch_bounds__(256) void split_kernel(const float* __restrict__ src, int ld,
                                                    __nv_bfloat16* __restrict__ h,
                                                    __nv_bfloat16* __restrict__ l) {
    const int row = blockIdx.x;
    const int c4 = threadIdx.x;
    float4 v = *(const float4*)(src + (size_t)row * ld + c4 * 4);
    unsigned h0 = pack_bf2(v.x, v.y);
    unsigned h1 = pack_bf2(v.z, v.w);
    unsigned l0 = pack_bf2(v.x - lo16f(h0), v.y - hi16f(h0));
    unsigned l1 = pack_bf2(v.z - lo16f(h1), v.w - hi16f(h1));
    *(uint2*)(h + (size_t)row * DDIM + c4 * 4) = make_uint2(h0, h1);
    *(uint2*)(l + (size_t)row * DDIM + c4 * 4) = make_uint2(l0, l1);
}

// ---------------- transpose-split: out[l][d] = src[d][l], bf16 hi/lo ----------------
__global__ __launch_bounds__(256) void tsplit_kernel(const float* __restrict__ src,
                                                     __nv_bfloat16* __restrict__ h,
                                                     __nv_bfloat16* __restrict__ l) {
    __shared__ float t[32][33];
    const int bx = blockIdx.x * 32;
    const int by = blockIdx.y * 32;
    const int tx = threadIdx.x & 31, ty = threadIdx.x >> 5;
    #pragma unroll
    for (int j = 0; j < 4; ++j)
        t[ty + j * 8][tx] = src[(size_t)(by + ty + j * 8) * DDIM + bx + tx];
    __syncthreads();
    #pragma unroll
    for (int j = 0; j < 4; ++j) {
        const int lrow = bx + ty + j * 8;
        const int dcol = by + tx;
        float v = t[tx][ty + j * 8];
        unsigned hb = pack_bf2(v, v);
        float hv = lo16f(hb);
        unsigned lb = pack_bf2(v - hv, v - hv);
        h[(size_t)lrow * DDIM + dcol] = *(__nv_bfloat16*)&hb;
        l[(size_t)lrow * DDIM + dcol] = *(__nv_bfloat16*)&lb;
    }
}

// ---------------- W2 -> fp16 ----------------
__global__ __launch_bounds__(256) void w2half_kernel(const float* __restrict__ W2,
                                                     __half* __restrict__ Wf) {
    int i = blockIdx.x * 256 + threadIdx.x;
    float4 v = ((const float4*)W2)[i];
    ((uint2*)Wf)[i] = make_uint2(pack_h2(v.x, v.y), pack_h2(v.z, v.w));
}

// ---------------- tensor GEMM: C[M,1024] = A @ B^T, bf16 3-term, occ 2 ----------------
#define GM_SA_H 0
#define GM_SA_L (128 * APAD * 2)
#define GM_SB_H (2 * 128 * APAD * 2)
#define GM_SB_L (3 * 128 * APAD * 2)
#define GM_SMEM (4 * 128 * APAD * 2)     // 73728

__global__ __launch_bounds__(256, 2) void gemm_mma_kernel(
    const __nv_bfloat16* __restrict__ Ah_g, const __nv_bfloat16* __restrict__ Al_g,
    const __nv_bfloat16* __restrict__ Bh_g, const __nv_bfloat16* __restrict__ Bl_g,
    float* __restrict__ C, int M) {
    extern __shared__ __align__(128) char sm[];
    const uint32_t sb = smem_to_u32(sm);
    const uint32_t sAh = sb + GM_SA_H, sAl = sb + GM_SA_L;
    const uint32_t sBh = sb + GM_SB_H, sBl = sb + GM_SB_L;

    const int tid = threadIdx.x;
    const int lane = tid & 31;
    const int wid = tid >> 5;
    const int warp_m = wid & 1, warp_n = wid >> 1;
    const int gid = lane >> 2, tig = lane & 3;
    const int row0 = blockIdx.y * 128, col0 = blockIdx.x * 128;

    const int rowA = lane & 15;
    const int colA = (lane >> 4) * 8;
    const int rowB = (lane & 7) + ((lane & 16) >> 1);
    const int colB = lane & 8;
    const uint32_t aoffL = (uint32_t)(rowA * (APAD * 2) + colA * 2);
    const uint32_t boffL = (uint32_t)(rowB * (APAD * 2) + colB * 2);

    const int am = tid >> 1;
    const int half = (tid & 1) * 32;
    const int gr = row0 + am;
    const int gc = col0 + am;

    float acc[4][4][4];
    #pragma unroll
    for (int mt = 0; mt < 4; ++mt)
        #pragma unroll
        for (int ntl = 0; ntl < 4; ++ntl)
            #pragma unroll
            for (int c = 0; c < 4; ++c) acc[mt][ntl][c] = 0.f;

    for (int kc = 0; kc < 16; ++kc) {
        const int k0 = kc * 64;
        __syncthreads();
        {
            const uint32_t dof = (uint32_t)(am * (APAD * 2) + half * 2);
            if (gr < M) {
                const uint4* aH = (const uint4*)(Ah_g + (size_t)gr * DDIM + k0 + half);
                const uint4* aL = (const uint4*)(Al_g + (size_t)gr * DDIM + k0 + half);
                #pragma unroll
                for (int q = 0; q < 4; ++q) {
                    *(uint4*)(sm + GM_SA_H + dof + q * 16) = aH[q];
                    *(uint4*)(sm + GM_SA_L + dof + q * 16) = aL[q];
                }
            } else {
                uint4 z = make_uint4(0, 0, 0, 0);
                #pragma unroll
                for (int q = 0; q < 4; ++q) {
                    *(uint4*)(sm + GM_SA_H + dof + q * 16) = z;
                    *(uint4*)(sm + GM_SA_L + dof + q * 16) = z;
                }
            }
            const uint4* bH = (const uint4*)(Bh_g + (size_t)gc * DDIM + k0 + half);
            const uint4* bL = (const uint4*)(Bl_g + (size_t)gc * DDIM + k0 + half);
            #pragma unroll
            for (int q = 0; q < 4; ++q) {
                *(uint4*)(sm + GM_SB_H + dof + q * 16) = bH[q];
                *(uint4*)(sm + GM_SB_L + dof + q * 16) = bL[q];
            }
        }
        __syncthreads();
        #pragma unroll
        for (int s = 0; s < 4; ++s) {
            const uint32_t cb2 = (uint32_t)(s * 32);
            unsigned ahi[4][4], alo[4][4];
            #pragma unroll
            for (int mt = 0; mt < 4; ++mt) {
                const uint32_t ra =
                    (uint32_t)((warp_m * 64 + mt * 16) * (APAD * 2)) + aoffL + cb2;
                ldsm4(ahi[mt], sAh + ra);
                ldsm4(alo[mt], sAl + ra);
            }
            #pragma unroll
            for (int p = 0; p < 2; ++p) {
                const uint32_t rb =
                    (uint32_t)((warp_n * 32 + p * 16) * (APAD * 2)) + boffL + cb2;
                unsigned bh[4], bl[4];
                ldsm4(bh, sBh + rb);
                ldsm4(bl, sBl + rb);
                #pragma unroll
                for (int h = 0; h < 2; ++h) {
                    const unsigned* bhp = bh + h * 2;
                    const unsigned* blp = bl + h * 2;
                    const int ntl = p * 2 + h;
                    #pragma unroll
                    for (int mt = 0; mt < 4; ++mt) mma_bf16(acc[mt][ntl], ahi[mt], bhp);
                    #pragma unroll
                    for (int mt = 0; mt < 4; ++mt) mma_bf16(acc[mt][ntl], alo[mt], bhp);
                    #pragma unroll
                    for (int mt = 0; mt < 4; ++mt) mma_bf16(acc[mt][ntl], ahi[mt], blp);
                }
            }
        }
    }
    #pragma unroll
    for (int mt = 0; mt < 4; ++mt) {
        const int r1 = row0 + warp_m * 64 + mt * 16 + gid;
        #pragma unroll
        for (int ntl = 0; ntl < 4; ++ntl) {
            const int cc = col0 + warp_n * 32 + ntl * 8 + tig * 2;
            if (r1 < M)
                *(float2*)(C + (size_t)r1 * DDIM + cc) =
                    make_float2(acc[mt][ntl][0], acc[mt][ntl][1]);
            if (r1 + 8 < M)
                *(float2*)(C + (size_t)(r1 + 8) * DDIM + cc) =
                    make_float2(acc[mt][ntl][2], acc[mt][ntl][3]);
        }
    }
}

// ---------------- fused: relu(hp+hl) @ W2f^T (fp16) -> relu -> dot W3 ----------------
// R12-measured version: M-tile 64, occ 2, in-kernel A staging (double-buffered),
// B via cp.async double buffer, one barrier per chunk.
#define FA_SZ  (64 * APAD * 2)            // 9216
#define FB_A   0                          // 2 x 9216 = 18432
#define FB_B   18432
#define FB_BSZ (256 * APAD * 2)           // 36864, x2 = 73728
#define FB_B2  (FB_B + 2 * FB_BSZ)        // 92160
#define FB_W3  (FB_B2 + 4096)
#define FB_LOG (FB_W3 + 4096)
#define FF_SMEM (FB_LOG + 256)            // 100608

__global__ __launch_bounds__(256, 2) void fused_f16_kernel(
    const float* __restrict__ hp, const float* __restrict__ hl,
    const __half* __restrict__ W2f, const float* __restrict__ b2,
    const float* __restrict__ W3, const float* __restrict__ b3,
    float* __restrict__ out) {
    extern __shared__ __align__(128) char sm[];
    const uint32_t sb = smem_to_u32(sm);
    float* b2s    = (float*)(sm + FB_B2);
    float* w3s    = (float*)(sm + FB_W3);
    float* logits = (float*)(sm + FB_LOG);

    const int tid = threadIdx.x;
    const int lane = tid & 31;
    const int wid = tid >> 5;
    const int warp_m = wid & 1, warp_n = wid >> 1;
    const int gid = lane >> 2, tig = lane & 3;
    const int r0 = blockIdx.x * 64;

    const int rowA = lane & 15;
    const int colA = (lane >> 4) * 8;
    const int rowB = (lane & 7) + ((lane & 16) >> 1);
    const int colB = lane & 8;
    const uint32_t aoffL = (uint32_t)(rowA * (APAD * 2) + colA * 2);
    const uint32_t boffL = (uint32_t)(rowB * (APAD * 2) + colB * 2);

    for (int i = tid; i < ODIM; i += 256) { b2s[i] = b2[i]; w3s[i] = W3[i]; }
    if (tid < 64) logits[tid] = 0.f;

    // A staging: 4 threads per row, 16 cols each
    const int am = tid >> 2;              // 0..63
    const int aq = (tid & 3) * 16;
    const int ar = r0 + am;
    const int ab = ar / NLBL;
    const int alr = ar - ab * NLBL;
    const float* hpA = hp + (size_t)ab * DDIM + aq;
    const float* hlA = hl + (size_t)alr * DDIM + aq;
    const uint32_t adst0 = (uint32_t)(FB_A + am * (APAD * 2) + aq * 2);

    // B prefetch: one W2 row per thread, 8 x 16B cp.async
    const uint32_t bdst0 = sb + FB_B + (uint32_t)(tid * (APAD * 2));

    float pr[4];
    #pragma unroll
    for (int i = 0; i < 4; ++i) pr[i] = 0.f;

    // ---- prologue: B chunk 0 + A chunk 0 into buffer 0
    {
        const __half* src = W2f + (size_t)tid * DDIM;
        #pragma unroll
        for (int g = 0; g < 8; ++g) CP_ASYNC16(bdst0 + g * 16, (const char*)src + g * 16);
        CP_COMMIT();
        #pragma unroll
        for (int j = 0; j < 4; ++j) {
            float4 p = *(const float4*)(hpA + j * 4);
            float4 q = *(const float4*)(hlA + j * 4);
            *(uint2*)(sm + adst0 + j * 8) =
                make_uint2(pack_h2(fmaxf(p.x + q.x, 0.f), fmaxf(p.y + q.y, 0.f)),
                           pack_h2(fmaxf(p.z + q.z, 0.f), fmaxf(p.w + q.w, 0.f)));
        }
        CP_WAIT0();
    }
    __syncthreads();

    for (int nt = 0; nt < 4; ++nt) {
        float acc[2][8][4];
        #pragma unroll
        for (int mt = 0; mt < 2; ++mt)
            #pragma unroll
            for (int ntl = 0; ntl < 8; ++ntl)
                #pragma unroll
                for (int c = 0; c < 4; ++c) acc[mt][ntl][c] = 0.f;

        for (int kc = 0; kc < 16; ++kc) {
            const int i = nt * 16 + kc;
            const int buf = i & 1;
            // ---- prefetch next B chunk
            if (i + 1 < 64) {
                const int ni = i + 1;
                const uint32_t dst = bdst0 + (uint32_t)((ni & 1) * FB_BSZ);
                const __half* src =
                    W2f + (size_t)((ni >> 4) * 256 + tid) * DDIM + (ni & 15) * 64;
                #pragma unroll
                for (int g = 0; g < 8; ++g)
                    CP_ASYNC16(dst + g * 16, (const char*)src + g * 16);
                CP_COMMIT();
            }
            // ---- mma on current buffers
            const uint32_t sA = sb + (uint32_t)(FB_A + buf * FA_SZ);
            const uint32_t sB = sb + (uint32_t)(FB_B + buf * FB_BSZ);
            #pragma unroll
            for (int s = 0; s < 4; ++s) {
                const uint32_t cb2 = (uint32_t)(s * 32);
                unsigned af[2][4];
                #pragma unroll
                for (int mt = 0; mt < 2; ++mt) {
                    const uint32_t ra =
                        (uint32_t)((warp_m * 32 + mt * 16) * (APAD * 2)) + aoffL + cb2;
                    ldsm4(af[mt], sA + ra);
                }
                #pragma unroll
                for (int p = 0; p < 4; ++p) {
                    const uint32_t rb =
                        (uint32_t)((warp_n * 64 + p * 16) * (APAD * 2)) + boffL + cb2;
                    unsigned bf[4];
                    ldsm4(bf, sB + rb);
                    #pragma unroll
                    for (int h = 0; h < 2; ++h) {
                        const unsigned* bp = bf + h * 2;
                        const int ntl = p * 2 + h;
                        #pragma unroll
                        for (int mt = 0; mt < 2; ++mt) mma_f16(acc[mt][ntl], af[mt], bp);
                    }
                }
            }
            // ---- stage next A chunk (depends only on k position)
            if (i + 1 < 64) {
                const int nk0 = ((i + 1) & 15) * 64;
                const uint32_t dst = (uint32_t)(((i + 1) & 1) * FA_SZ) + adst0;
                #pragma unroll
                for (int j = 0; j < 4; ++j) {
                    float4 p = *(const float4*)(hpA + nk0 + j * 4);
                    float4 q = *(const float4*)(hlA + nk0 + j * 4);
                    *(uint2*)(sm + dst + j * 8) =
                        make_uint2(pack_h2(fmaxf(p.x + q.x, 0.f), fmaxf(p.y + q.y, 0.f)),
                                   pack_h2(fmaxf(p.z + q.z, 0.f), fmaxf(p.w + q.w, 0.f)));
                }
            }
            CP_WAIT0();
            __syncthreads();   // next A staged by all warps + next B landed
        }
        // ---- fold this 256-col tile: relu(acc + b2) * W3 -> per-row partials
        #pragma unroll
        for (int mt = 0; mt < 2; ++mt)
            #pragma unroll
            for (int ntl = 0; ntl < 8; ++ntl) {
                const int colb = nt * 256 + warp_n * 64 + ntl * 8 + tig * 2;
                #pragma unroll
                for (int c = 0; c < 4; ++c) {
                    const int cc = colb + (c & 1);
                    float v = acc[mt][ntl][c] + b2s[cc];
                    pr[mt * 2 + (c >> 1)] =
                        fmaf(fmaxf(v, 0.f), w3s[cc], pr[mt * 2 + (c >> 1)]);
                }
            }
    }

    // reduce over lane quads, then across the 4 N-warps via smem atomics
    #pragma unroll
    for (int i2 = 0; i2 < 4; ++i2) {
        float v = pr[i2];
        v += __shfl_xor_sync(0xffffffffu, v, 1);
        v += __shfl_xor_sync(0xffffffffu, v, 2);
        if ((lane & 3) == 0)
            atomicAdd(&logits[warp_m * 32 + (i2 >> 1) * 16 + (i2 & 1) * 8 + gid], v);
    }
    __syncthreads();
    if (tid < 64) out[r0 + tid] = logits[tid] + b3[0];
}

// ---------------- launch ----------------
extern "C" void kernel_launch(void* const* d_in, const int* in_sizes, int n_in,
                              void* d_out, int out_size) {
    const float* seq    = (const float*)d_in[0];
    const float* labels = (const float*)d_in[1];
    const float* Wp     = (const float*)d_in[2];
    const float* Wl     = (const float*)d_in[3];
    const float* W1     = (const float*)d_in[4];
    const float* b1     = (const float*)d_in[5];
    const float* W2     = (const float*)d_in[6];
    const float* b2     = (const float*)d_in[7];
    const float* W3     = (const float*)d_in[8];
    const float* b3     = (const float*)d_in[9];
    float* out = (float*)d_out;

    float *Pe, *hp, *Wc, *hl;
    __nv_bfloat16 *LBh, *LBl, *WTh, *WTl, *W1h, *W1l, *Wch, *Wcl;
    __half* W2f;
    cudaGetSymbolAddress((void**)&Pe, g_Pe);
    cudaGetSymbolAddress((void**)&hp, g_hp);
    cudaGetSymbolAddress((void**)&Wc, g_Wc);
    cudaGetSymbolAddress((void**)&hl, g_hl);
    cudaGetSymbolAddress((void**)&LBh, g_LBh);
    cudaGetSymbolAddress((void**)&LBl, g_LBl);
    cudaGetSymbolAddress((void**)&WTh, g_WTh);
    cudaGetSymbolAddress((void**)&WTl, g_WTl);
    cudaGetSymbolAddress((void**)&W1h, g_W1h);
    cudaGetSymbolAddress((void**)&W1l, g_W1l);
    cudaGetSymbolAddress((void**)&Wch, g_Wch);
    cudaGetSymbolAddress((void**)&Wcl, g_Wcl);
    cudaGetSymbolAddress((void**)&W2f, g_W2f);

    pe_kernel<<<NB, 256>>>(seq, Wp, Pe);
    hp_kernel<<<NB, 256>>>(Pe, W1, b1, hp);

    // splits for the label-side algebra
    split_kernel<<<NLBL, 256>>>(labels, DDIM, LBh, LBl);
    split_kernel<<<DDIM, 256>>>(W1 + DDIM, 2 * DDIM, W1h, W1l);   // W1_l
    tsplit_kernel<<<dim3(32, 32), 256>>>(Wl, WTh, WTl);           // Wl^T

    cudaFuncSetAttribute(gemm_mma_kernel, cudaFuncAttributeMaxDynamicSharedMemorySize,
                         GM_SMEM);
    // Wc = W1_l @ Wl
    gemm_mma_kernel<<<dim3(8, 8), 256, GM_SMEM>>>(W1h, W1l, WTh, WTl, Wc, DDIM);
    split_kernel<<<DDIM, 256>>>(Wc, DDIM, Wch, Wcl);
    // hl = labels @ Wc^T
    gemm_mma_kernel<<<dim3(8, 40), 256, GM_SMEM>>>(LBh, LBl, Wch, Wcl, hl, NLBL);

    // W2 -> fp16
    w2half_kernel<<<(ODIM * DDIM / 4) / 256, 256>>>(W2, W2f);

    cudaFuncSetAttribute(fused_f16_kernel, cudaFuncAttributeMaxDynamicSharedMemorySize,
                         FF_SMEM);
    fused_f16_kernel<<<NROW / 64, 256, FF_SMEM>>>(hp, hl, W2f, b2, W3, b3, out);
}

// round 17
// speedup vs baseline: 1.1050x; 1.0586x over previous
#include <cuda_runtime.h>
#include <cuda_fp16.h>
#include <cuda_bf16.h>
#include <cstdint>
#include <cstddef>

#define PDIM 1100
#define DDIM 1024
#define ODIM 1024
#define NB   16
#define NLBL 5000
#define NROW (NB * NLBL)

// ---------------- scratch (static device globals; no runtime alloc) ----------------
__device__ float g_Pe[NB * DDIM];
__device__ float g_hp[NB * DDIM];        // hp = Pe @ W1_p^T + b1
__device__ float g_Wc[DDIM * DDIM];      // Wc = W1_l @ Wl
__device__ float g_hl[NLBL * DDIM];      // hl = labels @ Wc^T
__device__ __align__(16) __nv_bfloat16 g_LBh[NLBL * DDIM];   // reused as fp16 labels
__device__ __align__(16) __nv_bfloat16 g_WTh[DDIM * DDIM];
__device__ __align__(16) __nv_bfloat16 g_WTl[DDIM * DDIM];
__device__ __align__(16) __nv_bfloat16 g_W1h[DDIM * DDIM];
__device__ __align__(16) __nv_bfloat16 g_W1l[DDIM * DDIM];
__device__ __align__(16) __nv_bfloat16 g_Wch[DDIM * DDIM];   // reused as fp16 Wc
__device__ __align__(16) __half g_W2f[ODIM * DDIM];          // fp16 W2

// ---------------- pack helpers ----------------
__device__ __forceinline__ unsigned pack_bf2(float lo_elem, float hi_elem) {
    unsigned r;
    asm("cvt.rn.bf16x2.f32 %0, %1, %2;" : "=r"(r) : "f"(hi_elem), "f"(lo_elem));
    return r;
}
__device__ __forceinline__ unsigned pack_h2(float lo_elem, float hi_elem) {
    unsigned r;
    asm("cvt.rn.f16x2.f32 %0, %1, %2;" : "=r"(r) : "f"(hi_elem), "f"(lo_elem));
    return r;
}
__device__ __forceinline__ float lo16f(unsigned u) { return __uint_as_float(u << 16); }
__device__ __forceinline__ float hi16f(unsigned u) { return __uint_as_float(u & 0xffff0000u); }

// ---------------- mma.sync + ldmatrix + cp.async (standard PTX, base sm_103) ----------------
__device__ __forceinline__ void mma_bf16(float* c, const unsigned* a, const unsigned* b) {
    asm volatile(
        "mma.sync.aligned.m16n8k16.row.col.f32.bf16.bf16.f32 "
        "{%0,%1,%2,%3}, {%4,%5,%6,%7}, {%8,%9}, {%0,%1,%2,%3};"
        : "+f"(c[0]), "+f"(c[1]), "+f"(c[2]), "+f"(c[3])
        : "r"(a[0]), "r"(a[1]), "r"(a[2]), "r"(a[3]), "r"(b[0]), "r"(b[1]));
}
__device__ __forceinline__ void mma_f16(float* c, const unsigned* a, const unsigned* b) {
    asm volatile(
        "mma.sync.aligned.m16n8k16.row.col.f32.f16.f16.f32 "
        "{%0,%1,%2,%3}, {%4,%5,%6,%7}, {%8,%9}, {%0,%1,%2,%3};"
        : "+f"(c[0]), "+f"(c[1]), "+f"(c[2]), "+f"(c[3])
        : "r"(a[0]), "r"(a[1]), "r"(a[2]), "r"(a[3]), "r"(b[0]), "r"(b[1]));
}
__device__ __forceinline__ void ldsm4(unsigned* r, uint32_t addr) {
    asm volatile("ldmatrix.sync.aligned.m8n8.x4.shared.b16 {%0,%1,%2,%3}, [%4];"
                 : "=r"(r[0]), "=r"(r[1]), "=r"(r[2]), "=r"(r[3]) : "r"(addr));
}
__device__ __forceinline__ uint32_t smem_to_u32(const void* p) {
    uint32_t a;
    asm("{ .reg .u64 t; cvta.to.shared.u64 t, %1; cvt.u32.u64 %0, t; }" : "=r"(a) : "l"(p));
    return a;
}
#define CP_ASYNC16(dst, src) \
    asm volatile("cp.async.cg.shared.global [%0], [%1], 16;" :: "r"(dst), "l"(src))
#define CP_COMMIT() asm volatile("cp.async.commit_group;" ::: "memory")
#define CP_WAIT0()  asm volatile("cp.async.wait_group 0;" ::: "memory")

#define APAD 72   // 144 B rows -> conflict-free ldmatrix phases

// ---------------- kernel 1a: Pe[b, :] = seq[b, :] @ Wp^T ----------------
__global__ __launch_bounds__(256) void pe_kernel(const float* __restrict__ seq,
                                                 const float* __restrict__ Wp,
                                                 float* __restrict__ Pe) {
    __shared__ float s[PDIM];
    const int b = blockIdx.x, tid = threadIdx.x;
    for (int i = tid; i < PDIM; i += 256) s[i] = seq[b * PDIM + i];
    __syncthreads();
    const int warp = tid >> 5, lane = tid & 31;
    for (int d = warp; d < DDIM; d += 8) {
        const float* wrow = Wp + (size_t)d * PDIM;
        float p = 0.f;
        for (int k = lane; k < PDIM; k += 32) p = fmaf(s[k], wrow[k], p);
        #pragma unroll
        for (int off = 16; off > 0; off >>= 1) p += __shfl_down_sync(0xffffffffu, p, off);
        if (lane == 0) Pe[b * DDIM + d] = p;
    }
}

// ---------------- kernel 1b: hp[b, :] = Pe[b, :] @ W1_p^T + b1 ----------------
__global__ __launch_bounds__(256) void hp_kernel(const float* __restrict__ Pe,
                                                 const float* __restrict__ W1,
                                                 const float* __restrict__ b1,
                                                 float* __restrict__ hp) {
    __shared__ float s[DDIM];
    const int b = blockIdx.x, tid = threadIdx.x;
    for (int i = tid; i < DDIM; i += 256) s[i] = Pe[b * DDIM + i];
    __syncthreads();
    const int warp = tid >> 5, lane = tid & 31;
    for (int o = warp; o < ODIM; o += 8) {
        const float* wrow = W1 + (size_t)o * (2 * DDIM);
        float p = 0.f;
        for (int k = lane; k < DDIM; k += 32) p = fmaf(s[k], wrow[k], p);
        #pragma unroll
        for (int off = 16; off > 0; off >>= 1) p += __shfl_down_sync(0xffffffffu, p, off);
        if (lane == 0) hp[b * DDIM + o] = p + b1[o];
    }
}

// ---------------- split: fp32 rows (stride ld) -> bf16 hi/lo ----------------
__global__ __launch_bounds__(256) void split_kernel(const float* __restrict__ src, int ld,
                                                    __nv_bfloat16* __restrict__ h,
                                                    __nv_bfloat16* __restrict__ l) {
    const int row = blockIdx.x;
    const int c4 = threadIdx.x;
    float4 v = *(const float4*)(src + (size_t)row * ld + c4 * 4);
    unsigned h0 = pack_bf2(v.x, v.y);
    unsigned h1 = pack_bf2(v.z, v.w);
    unsigned l0 = pack_bf2(v.x - lo16f(h0), v.y - hi16f(h0));
    unsigned l1 = pack_bf2(v.z - lo16f(h1), v.w - hi16f(h1));
    *(uint2*)(h + (size_t)row * DDIM + c4 * 4) = make_uint2(h0, h1);
    *(uint2*)(l + (size_t)row * DDIM + c4 * 4) = make_uint2(l0, l1);
}

// ---------------- transpose-split: out[l][d] = src[d][l], bf16 hi/lo ----------------
__global__ __launch_bounds__(256) void tsplit_kernel(const float* __restrict__ src,
                                                     __nv_bfloat16* __restrict__ h,
                                                     __nv_bfloat16* __restrict__ l) {
    __shared__ float t[32][33];
    const int bx = blockIdx.x * 32;
    const int by = blockIdx.y * 32;
    const int tx = threadIdx.x & 31, ty = threadIdx.x >> 5;
    #pragma unroll
    for (int j = 0; j < 4; ++j)
        t[ty + j * 8][tx] = src[(size_t)(by + ty + j * 8) * DDIM + bx + tx];
    __syncthreads();
    #pragma unroll
    for (int j = 0; j < 4; ++j) {
        const int lrow = bx + ty + j * 8;
        const int dcol = by + tx;
        float v = t[tx][ty + j * 8];
        unsigned hb = pack_bf2(v, v);
        float hv = lo16f(hb);
        unsigned lb = pack_bf2(v - hv, v - hv);
        h[(size_t)lrow * DDIM + dcol] = *(__nv_bfloat16*)&hb;
        l[(size_t)lrow * DDIM + dcol] = *(__nv_bfloat16*)&lb;
    }
}

// ---------------- generic fp32 -> fp16 convert (1024 floats per block) ----------------
__global__ __launch_bounds__(256) void tohalf_kernel(const float* __restrict__ src,
                                                     __half* __restrict__ dst) {
    int i = blockIdx.x * 256 + threadIdx.x;
    float4 v = ((const float4*)src)[i];
    ((uint2*)dst)[i] = make_uint2(pack_h2(v.x, v.y), pack_h2(v.z, v.w));
}

// ---------------- tensor GEMM (bf16 3-term): C[M,1024] = A @ B^T ----------------
#define GM_SA_H 0
#define GM_SA_L (128 * APAD * 2)
#define GM_SB_H (2 * 128 * APAD * 2)
#define GM_SB_L (3 * 128 * APAD * 2)
#define GM_SMEM (4 * 128 * APAD * 2)     // 73728

__global__ __launch_bounds__(256, 2) void gemm_mma_kernel(
    const __nv_bfloat16* __restrict__ Ah_g, const __nv_bfloat16* __restrict__ Al_g,
    const __nv_bfloat16* __restrict__ Bh_g, const __nv_bfloat16* __restrict__ Bl_g,
    float* __restrict__ C, int M) {
    extern __shared__ __align__(128) char sm[];
    const uint32_t sb = smem_to_u32(sm);
    const uint32_t sAh = sb + GM_SA_H, sAl = sb + GM_SA_L;
    const uint32_t sBh = sb + GM_SB_H, sBl = sb + GM_SB_L;

    const int tid = threadIdx.x;
    const int lane = tid & 31;
    const int wid = tid >> 5;
    const int warp_m = wid & 1, warp_n = wid >> 1;
    const int gid = lane >> 2, tig = lane & 3;
    const int row0 = blockIdx.y * 128, col0 = blockIdx.x * 128;

    const int rowA = lane & 15;
    const int colA = (lane >> 4) * 8;
    const int rowB = (lane & 7) + ((lane & 16) >> 1);
    const int colB = lane & 8;
    const uint32_t aoffL = (uint32_t)(rowA * (APAD * 2) + colA * 2);
    const uint32_t boffL = (uint32_t)(rowB * (APAD * 2) + colB * 2);

    const int am = tid >> 1;
    const int half = (tid & 1) * 32;
    const int gr = row0 + am;
    const int gc = col0 + am;

    float acc[4][4][4];
    #pragma unroll
    for (int mt = 0; mt < 4; ++mt)
        #pragma unroll
        for (int ntl = 0; ntl < 4; ++ntl)
            #pragma unroll
            for (int c = 0; c < 4; ++c) acc[mt][ntl][c] = 0.f;

    for (int kc = 0; kc < 16; ++kc) {
        const int k0 = kc * 64;
        __syncthreads();
        {
            const uint32_t dof = (uint32_t)(am * (APAD * 2) + half * 2);
            if (gr < M) {
                const uint4* aH = (const uint4*)(Ah_g + (size_t)gr * DDIM + k0 + half);
                const uint4* aL = (const uint4*)(Al_g + (size_t)gr * DDIM + k0 + half);
                #pragma unroll
                for (int q = 0; q < 4; ++q) {
                    *(uint4*)(sm + GM_SA_H + dof + q * 16) = aH[q];
                    *(uint4*)(sm + GM_SA_L + dof + q * 16) = aL[q];
                }
            } else {
                uint4 z = make_uint4(0, 0, 0, 0);
                #pragma unroll
                for (int q = 0; q < 4; ++q) {
                    *(uint4*)(sm + GM_SA_H + dof + q * 16) = z;
                    *(uint4*)(sm + GM_SA_L + dof + q * 16) = z;
                }
            }
            const uint4* bH = (const uint4*)(Bh_g + (size_t)gc * DDIM + k0 + half);
            const uint4* bL = (const uint4*)(Bl_g + (size_t)gc * DDIM + k0 + half);
            #pragma unroll
            for (int q = 0; q < 4; ++q) {
                *(uint4*)(sm + GM_SB_H + dof + q * 16) = bH[q];
                *(uint4*)(sm + GM_SB_L + dof + q * 16) = bL[q];
            }
        }
        __syncthreads();
        #pragma unroll
        for (int s = 0; s < 4; ++s) {
            const uint32_t cb2 = (uint32_t)(s * 32);
            unsigned ahi[4][4], alo[4][4];
            #pragma unroll
            for (int mt = 0; mt < 4; ++mt) {
                const uint32_t ra =
                    (uint32_t)((warp_m * 64 + mt * 16) * (APAD * 2)) + aoffL + cb2;
                ldsm4(ahi[mt], sAh + ra);
                ldsm4(alo[mt], sAl + ra);
            }
            #pragma unroll
            for (int p = 0; p < 2; ++p) {
                const uint32_t rb =
                    (uint32_t)((warp_n * 32 + p * 16) * (APAD * 2)) + boffL + cb2;
                unsigned bh[4], bl[4];
                ldsm4(bh, sBh + rb);
                ldsm4(bl, sBl + rb);
                #pragma unroll
                for (int h = 0; h < 2; ++h) {
                    const unsigned* bhp = bh + h * 2;
                    const unsigned* blp = bl + h * 2;
                    const int ntl = p * 2 + h;
                    #pragma unroll
                    for (int mt = 0; mt < 4; ++mt) mma_bf16(acc[mt][ntl], ahi[mt], bhp);
                    #pragma unroll
                    for (int mt = 0; mt < 4; ++mt) mma_bf16(acc[mt][ntl], alo[mt], bhp);
                    #pragma unroll
                    for (int mt = 0; mt < 4; ++mt) mma_bf16(acc[mt][ntl], ahi[mt], blp);
                }
            }
        }
    }
    #pragma unroll
    for (int mt = 0; mt < 4; ++mt) {
        const int r1 = row0 + warp_m * 64 + mt * 16 + gid;
        #pragma unroll
        for (int ntl = 0; ntl < 4; ++ntl) {
            const int cc = col0 + warp_n * 32 + ntl * 8 + tig * 2;
            if (r1 < M)
                *(float2*)(C + (size_t)r1 * DDIM + cc) =
                    make_float2(acc[mt][ntl][0], acc[mt][ntl][1]);
            if (r1 + 8 < M)
                *(float2*)(C + (size_t)(r1 + 8) * DDIM + cc) =
                    make_float2(acc[mt][ntl][2], acc[mt][ntl][3]);
        }
    }
}

// ---------------- tensor GEMM (fp16 single-term): C[M,1024] = A @ B^T ----------------
#define GF_SA 0
#define GF_SB (128 * APAD * 2)
#define GF_SMEM (2 * 128 * APAD * 2)     // 36864

__global__ __launch_bounds__(256, 2) void gemm_f16_kernel(
    const __half* __restrict__ Af, const __half* __restrict__ Bf,
    float* __restrict__ C, int M) {
    extern __shared__ __align__(128) char sm[];
    const uint32_t sb = smem_to_u32(sm);
    const uint32_t sA = sb + GF_SA, sB = sb + GF_SB;

    const int tid = threadIdx.x;
    const int lane = tid & 31;
    const int wid = tid >> 5;
    const int warp_m = wid & 1, warp_n = wid >> 1;
    const int gid = lane >> 2, tig = lane & 3;
    const int row0 = blockIdx.y * 128, col0 = blockIdx.x * 128;

    const int rowA = lane & 15;
    const int colA = (lane >> 4) * 8;
    const int rowB = (lane & 7) + ((lane & 16) >> 1);
    const int colB = lane & 8;
    const uint32_t aoffL = (uint32_t)(rowA * (APAD * 2) + colA * 2);
    const uint32_t boffL = (uint32_t)(rowB * (APAD * 2) + colB * 2);

    const int am = tid >> 1;
    const int half = (tid & 1) * 32;
    const int gr = row0 + am;
    const int gc = col0 + am;

    float acc[4][4][4];
    #pragma unroll
    for (int mt = 0; mt < 4; ++mt)
        #pragma unroll
        for (int ntl = 0; ntl < 4; ++ntl)
            #pragma unroll
            for (int c = 0; c < 4; ++c) acc[mt][ntl][c] = 0.f;

    for (int kc = 0; kc < 16; ++kc) {
        const int k0 = kc * 64;
        __syncthreads();
        {
            const uint32_t dof = (uint32_t)(am * (APAD * 2) + half * 2);
            if (gr < M) {
                const uint4* aS = (const uint4*)(Af + (size_t)gr * DDIM + k0 + half);
                #pragma unroll
                for (int q = 0; q < 4; ++q)
                    *(uint4*)(sm + GF_SA + dof + q * 16) = aS[q];
            } else {
                uint4 z = make_uint4(0, 0, 0, 0);
                #pragma unroll
                for (int q = 0; q < 4; ++q)
                    *(uint4*)(sm + GF_SA + dof + q * 16) = z;
            }
            const uint4* bS = (const uint4*)(Bf + (size_t)gc * DDIM + k0 + half);
            #pragma unroll
            for (int q = 0; q < 4; ++q)
                *(uint4*)(sm + GF_SB + dof + q * 16) = bS[q];
        }
        __syncthreads();
        #pragma unroll
        for (int s = 0; s < 4; ++s) {
            const uint32_t cb2 = (uint32_t)(s * 32);
            unsigned af[4][4];
            #pragma unroll
            for (int mt = 0; mt < 4; ++mt) {
                const uint32_t ra =
                    (uint32_t)((warp_m * 64 + mt * 16) * (APAD * 2)) + aoffL + cb2;
                ldsm4(af[mt], sA + ra);
            }
            #pragma unroll
            for (int p = 0; p < 2; ++p) {
                const uint32_t rb =
                    (uint32_t)((warp_n * 32 + p * 16) * (APAD * 2)) + boffL + cb2;
                unsigned bf[4];
                ldsm4(bf, sB + rb);
                #pragma unroll
                for (int h = 0; h < 2; ++h) {
                    const unsigned* bp = bf + h * 2;
                    const int ntl = p * 2 + h;
                    #pragma unroll
                    for (int mt = 0; mt < 4; ++mt) mma_f16(acc[mt][ntl], af[mt], bp);
                }
            }
        }
    }
    #pragma unroll
    for (int mt = 0; mt < 4; ++mt) {
        const int r1 = row0 + warp_m * 64 + mt * 16 + gid;
        #pragma unroll
        for (int ntl = 0; ntl < 4; ++ntl) {
            const int cc = col0 + warp_n * 32 + ntl * 8 + tig * 2;
            if (r1 < M)
                *(float2*)(C + (size_t)r1 * DDIM + cc) =
                    make_float2(acc[mt][ntl][0], acc[mt][ntl][1]);
            if (r1 + 8 < M)
                *(float2*)(C + (size_t)(r1 + 8) * DDIM + cc) =
                    make_float2(acc[mt][ntl][2], acc[mt][ntl][3]);
        }
    }
}

// ---------------- fused: relu(hp+hl) @ W2f^T (fp16) -> relu -> dot W3 ----------------
// R12-measured version: M-tile 64, occ 2, in-kernel A staging (double-buffered),
// B via cp.async double buffer, one barrier per chunk.
#define FA_SZ  (64 * APAD * 2)            // 9216
#define FB_A   0                          // 2 x 9216 = 18432
#define FB_B   18432
#define FB_BSZ (256 * APAD * 2)           // 36864, x2 = 73728
#define FB_B2  (FB_B + 2 * FB_BSZ)        // 92160
#define FB_W3  (FB_B2 + 4096)
#define FB_LOG (FB_W3 + 4096)
#define FF_SMEM (FB_LOG + 256)            // 100608

__global__ __launch_bounds__(256, 2) void fused_f16_kernel(
    const float* __restrict__ hp, const float* __restrict__ hl,
    const __half* __restrict__ W2f, const float* __restrict__ b2,
    const float* __restrict__ W3, const float* __restrict__ b3,
    float* __restrict__ out) {
    extern __shared__ __align__(128) char sm[];
    const uint32_t sb = smem_to_u32(sm);
    float* b2s    = (float*)(sm + FB_B2);
    float* w3s    = (float*)(sm + FB_W3);
    float* logits = (float*)(sm + FB_LOG);

    const int tid = threadIdx.x;
    const int lane = tid & 31;
    const int wid = tid >> 5;
    const int warp_m = wid & 1, warp_n = wid >> 1;
    const int gid = lane >> 2, tig = lane & 3;
    const int r0 = blockIdx.x * 64;

    const int rowA = lane & 15;
    const int colA = (lane >> 4) * 8;
    const int rowB = (lane & 7) + ((lane & 16) >> 1);
    const int colB = lane & 8;
    const uint32_t aoffL = (uint32_t)(rowA * (APAD * 2) + colA * 2);
    const uint32_t boffL = (uint32_t)(rowB * (APAD * 2) + colB * 2);

    for (int i = tid; i < ODIM; i += 256) { b2s[i] = b2[i]; w3s[i] = W3[i]; }
    if (tid < 64) logits[tid] = 0.f;

    // A staging: 4 threads per row, 16 cols each
    const int am = tid >> 2;              // 0..63
    const int aq = (tid & 3) * 16;
    const int ar = r0 + am;
    const int ab = ar / NLBL;
    const int alr = ar - ab * NLBL;
    const float* hpA = hp + (size_t)ab * DDIM + aq;
    const float* hlA = hl + (size_t)alr * DDIM + aq;
    const uint32_t adst0 = (uint32_t)(FB_A + am * (APAD * 2) + aq * 2);

    // B prefetch: one W2 row per thread, 8 x 16B cp.async
    const uint32_t bdst0 = sb + FB_B + (uint32_t)(tid * (APAD * 2));

    float pr[4];
    #pragma unroll
    for (int i = 0; i < 4; ++i) pr[i] = 0.f;

    // ---- prologue: B chunk 0 + A chunk 0 into buffer 0
    {
        const __half* src = W2f + (size_t)tid * DDIM;
        #pragma unroll
        for (int g = 0; g < 8; ++g) CP_ASYNC16(bdst0 + g * 16, (const char*)src + g * 16);
        CP_COMMIT();
        #pragma unroll
        for (int j = 0; j < 4; ++j) {
            float4 p = *(const float4*)(hpA + j * 4);
            float4 q = *(const float4*)(hlA + j * 4);
            *(uint2*)(sm + adst0 + j * 8) =
                make_uint2(pack_h2(fmaxf(p.x + q.x, 0.f), fmaxf(p.y + q.y, 0.f)),
                           pack_h2(fmaxf(p.z + q.z, 0.f), fmaxf(p.w + q.w, 0.f)));
        }
        CP_WAIT0();
    }
    __syncthreads();

    for (int nt = 0; nt < 4; ++nt) {
        float acc[2][8][4];
        #pragma unroll
        for (int mt = 0; mt < 2; ++mt)
            #pragma unroll
            for (int ntl = 0; ntl < 8; ++ntl)
                #pragma unroll
                for (int c = 0; c < 4; ++c) acc[mt][ntl][c] = 0.f;

        for (int kc = 0; kc < 16; ++kc) {
            const int i = nt * 16 + kc;
            const int buf = i & 1;
            // ---- prefetch next B chunk
            if (i + 1 < 64) {
                const int ni = i + 1;
                const uint32_t dst = bdst0 + (uint32_t)((ni & 1) * FB_BSZ);
                const __half* src =
                    W2f + (size_t)((ni >> 4) * 256 + tid) * DDIM + (ni & 15) * 64;
                #pragma unroll
                for (int g = 0; g < 8; ++g)
                    CP_ASYNC16(dst + g * 16, (const char*)src + g * 16);
                CP_COMMIT();
            }
            // ---- mma on current buffers
            const uint32_t sA = sb + (uint32_t)(FB_A + buf * FA_SZ);
            const uint32_t sB = sb + (uint32_t)(FB_B + buf * FB_BSZ);
            #pragma unroll
            for (int s = 0; s < 4; ++s) {
                const uint32_t cb2 = (uint32_t)(s * 32);
                unsigned af[2][4];
                #pragma unroll
                for (int mt = 0; mt < 2; ++mt) {
                    const uint32_t ra =
                        (uint32_t)((warp_m * 32 + mt * 16) * (APAD * 2)) + aoffL + cb2;
                    ldsm4(af[mt], sA + ra);
                }
                #pragma unroll
                for (int p = 0; p < 4; ++p) {
                    const uint32_t rb =
                        (uint32_t)((warp_n * 64 + p * 16) * (APAD * 2)) + boffL + cb2;
                    unsigned bf[4];
                    ldsm4(bf, sB + rb);
                    #pragma unroll
                    for (int h = 0; h < 2; ++h) {
                        const unsigned* bp = bf + h * 2;
                        const int ntl = p * 2 + h;
                        #pragma unroll
                        for (int mt = 0; mt < 2; ++mt) mma_f16(acc[mt][ntl], af[mt], bp);
                    }
                }
            }
            // ---- stage next A chunk (depends only on k position)
            if (i + 1 < 64) {
                const int nk0 = ((i + 1) & 15) * 64;
                const uint32_t dst = (uint32_t)(((i + 1) & 1) * FA_SZ) + adst0;
                #pragma unroll
                for (int j = 0; j < 4; ++j) {
                    float4 p = *(const float4*)(hpA + nk0 + j * 4);
                    float4 q = *(const float4*)(hlA + nk0 + j * 4);
                    *(uint2*)(sm + dst + j * 8) =
                        make_uint2(pack_h2(fmaxf(p.x + q.x, 0.f), fmaxf(p.y + q.y, 0.f)),
                                   pack_h2(fmaxf(p.z + q.z, 0.f), fmaxf(p.w + q.w, 0.f)));
                }
            }
            CP_WAIT0();
            __syncthreads();   // next A staged by all warps + next B landed
        }
        // ---- fold this 256-col tile: relu(acc + b2) * W3 -> per-row partials
        #pragma unroll
        for (int mt = 0; mt < 2; ++mt)
            #pragma unroll
            for (int ntl = 0; ntl < 8; ++ntl) {
                const int colb = nt * 256 + warp_n * 64 + ntl * 8 + tig * 2;
                #pragma unroll
                for (int c = 0; c < 4; ++c) {
                    const int cc = colb + (c & 1);
                    float v = acc[mt][ntl][c] + b2s[cc];
                    pr[mt * 2 + (c >> 1)] =
                        fmaf(fmaxf(v, 0.f), w3s[cc], pr[mt * 2 + (c >> 1)]);
                }
            }
    }

    // reduce over lane quads, then across the 4 N-warps via smem atomics
    #pragma unroll
    for (int i2 = 0; i2 < 4; ++i2) {
        float v = pr[i2];
        v += __shfl_xor_sync(0xffffffffu, v, 1);
        v += __shfl_xor_sync(0xffffffffu, v, 2);
        if ((lane & 3) == 0)
            atomicAdd(&logits[warp_m * 32 + (i2 >> 1) * 16 + (i2 & 1) * 8 + gid], v);
    }
    __syncthreads();
    if (tid < 64) out[r0 + tid] = logits[tid] + b3[0];
}

// ---------------- launch ----------------
extern "C" void kernel_launch(void* const* d_in, const int* in_sizes, int n_in,
                              void* d_out, int out_size) {
    const float* seq    = (const float*)d_in[0];
    const float* labels = (const float*)d_in[1];
    const float* Wp     = (const float*)d_in[2];
    const float* Wl     = (const float*)d_in[3];
    const float* W1     = (const float*)d_in[4];
    const float* b1     = (const float*)d_in[5];
    const float* W2     = (const float*)d_in[6];
    const float* b2     = (const float*)d_in[7];
    const float* W3     = (const float*)d_in[8];
    const float* b3     = (const float*)d_in[9];
    float* out = (float*)d_out;

    float *Pe, *hp, *Wc, *hl;
    __nv_bfloat16 *LBh, *WTh, *WTl, *W1h, *W1l, *Wch;
    __half* W2f;
    cudaGetSymbolAddress((void**)&Pe, g_Pe);
    cudaGetSymbolAddress((void**)&hp, g_hp);
    cudaGetSymbolAddress((void**)&Wc, g_Wc);
    cudaGetSymbolAddress((void**)&hl, g_hl);
    cudaGetSymbolAddress((void**)&LBh, g_LBh);
    cudaGetSymbolAddress((void**)&WTh, g_WTh);
    cudaGetSymbolAddress((void**)&WTl, g_WTl);
    cudaGetSymbolAddress((void**)&W1h, g_W1h);
    cudaGetSymbolAddress((void**)&W1l, g_W1l);
    cudaGetSymbolAddress((void**)&Wch, g_Wch);
    cudaGetSymbolAddress((void**)&W2f, g_W2f);
    __half* L16  = (__half*)LBh;   // fp16 labels (reuses bf16 buffer, same size)
    __half* Wc16 = (__half*)Wch;   // fp16 Wc

    pe_kernel<<<NB, 256>>>(seq, Wp, Pe);
    hp_kernel<<<NB, 256>>>(Pe, W1, b1, hp);

    // splits for the Wc (bf16x3) GEMM only
    split_kernel<<<DDIM, 256>>>(W1 + DDIM, 2 * DDIM, W1h, W1l);   // W1_l
    tsplit_kernel<<<dim3(32, 32), 256>>>(Wl, WTh, WTl);           // Wl^T

    cudaFuncSetAttribute(gemm_mma_kernel, cudaFuncAttributeMaxDynamicSharedMemorySize,
                         GM_SMEM);
    // Wc = W1_l @ Wl  (bf16 3-term, accuracy-critical: feeds everything)
    gemm_mma_kernel<<<dim3(8, 8), 256, GM_SMEM>>>(W1h, W1l, WTh, WTl, Wc, DDIM);

    // fp16 operands for the label GEMM
    tohalf_kernel<<<DDIM, 256>>>(Wc, Wc16);
    tohalf_kernel<<<NLBL, 256>>>(labels, L16);

    cudaFuncSetAttribute(gemm_f16_kernel, cudaFuncAttributeMaxDynamicSharedMemorySize,
                         GF_SMEM);
    // hl = labels @ Wc^T  (fp16 single-term, 3x fewer HMMA)
    gemm_f16_kernel<<<dim3(8, 40), 256, GF_SMEM>>>(L16, Wc16, hl, NLBL);

    // W2 -> fp16
    tohalf_kernel<<<ODIM, 256>>>(W2, W2f);

    cudaFuncSetAttribute(fused_f16_kernel, cudaFuncAttributeMaxDynamicSharedMemorySize,
                         FF_SMEM);
    fused_f16_kernel<<<NROW / 64, 256, FF_SMEM>>>(hp, hl, W2f, b2, W3, b3, out);
}